// round 9
// baseline (speedup 1.0000x reference)
#include <cuda_runtime.h>
#include <math.h>
#include <float.h>

// Problem constants
#define BB 4
#define NN 256
#define DD 256
#define HH 4
#define DH 64
#define INNER 256
#define LL 2
#define FFH 1024
#define FFHALF 512
#define MAXE (BB*NN*16)
#define EBSZ (BB*NN*NN*HH)

typedef unsigned long long ull;

// ---------------- device scratch ----------------
__device__ float g_x   [BB*NN*DD];
__device__ float g_xn  [BB*NN*DD];
__device__ float g_qkv [BB*NN*768];
__device__ float g_wqkv[LL*DD*768];
__device__ float g_eb  [LL*EBSZ];            // per-layer edge bias
__device__ float g_attn[BB*HH*NN*NN];
__device__ float g_Ag  [HH*BB*NN*INNER];
__device__ float g_tmp [BB*NN*INNER];
__device__ float g_hg  [BB*NN*FFH];
__device__ unsigned char g_adj[BB*NN*NN];
__device__ int   g_valid[BB*NN];
__device__ float g_ls[BB];
__device__ int   g_elist[MAXE];
__device__ int   g_ecnt;

__device__ __forceinline__ float gelu_f(float x) {
    return 0.5f * x * (1.0f + erff(x * 0.70710678118654752440f));
}
__device__ __forceinline__ int hop_of(int n) {
    return (n == 0) ? 0 : ((n < 128) ? 1 : 2);
}
__device__ __forceinline__ float wredsum(float v) {
#pragma unroll
    for (int o = 16; o; o >>= 1) v += __shfl_xor_sync(0xffffffffu, v, o);
    return v;
}
__device__ __forceinline__ float wredmax(float v) {
#pragma unroll
    for (int o = 16; o; o >>= 1) v = fmaxf(v, __shfl_xor_sync(0xffffffffu, v, o));
    return v;
}

// ---------------- f32x2 packed FMA helpers ----------------
__device__ __forceinline__ void ffma2(ull& acc, ull a, ull b) {
    asm("fma.rn.f32x2 %0, %1, %2, %0;" : "+l"(acc) : "l"(a), "l"(b));
}
__device__ __forceinline__ ull pack_dup(float x) {
    ull r;
    asm("mov.b64 %0, {%1, %1};" : "=l"(r) : "f"(x));
    return r;
}
__device__ __forceinline__ float2 unpack2(ull v) {
    float2 f;
    asm("mov.b64 {%0, %1}, %2;" : "=f"(f.x), "=f"(f.y) : "l"(v));
    return f;
}

// ---------------- copy out ----------------
__global__ void k_copy_out(float* __restrict__ dst) {
    int i = blockIdx.x * blockDim.x + threadIdx.x;
    ((float4*)dst)[i] = ((const float4*)g_x)[i];
}

// ---------------- copy in + validity (fused) ----------------
__global__ void __launch_bounds__(256) k_loadx(const float* __restrict__ src) {
    int row = blockIdx.x, t = threadIdx.x;
    float v = src[(size_t)row * DD + t];
    g_x[(size_t)row * DD + t] = v;
    __shared__ float s8[8];
    float ws = wredsum(fabsf(v));
    if ((t & 31) == 0) s8[t >> 5] = ws;
    __syncthreads();
    if (t == 0) {
        float s = 0.f;
#pragma unroll
        for (int k = 0; k < 8; k++) s += s8[k];
        int n = row & 255;
        g_valid[row] = (s > 0.f) || (n == 0);
        if (row == 0) g_ecnt = 0;
    }
}

// ---------------- pack QKV weights ----------------
__global__ void k_pack(const float* __restrict__ Wq, const float* __restrict__ Wk,
                       const float* __restrict__ Wv) {
    int idx = blockIdx.x * blockDim.x + threadIdx.x;
    int l = idx / (DD * 768);
    int rem = idx % (DD * 768);
    int k = rem / 768, c = rem % 768;
    int z = c >> 8, n = c & 255;
    const float* src = (z == 0) ? Wq : ((z == 1) ? Wk : Wv);
    g_wqkv[idx] = src[(size_t)l * DD * INNER + k * INNER + n];
}

// ---------------- base adjacency fill ----------------
__global__ void __launch_bounds__(64) k_adj_fill() {
    int row = blockIdx.x;
    int b = row >> 8, i = row & 255;
    int t = threadIdx.x;
    int vi = g_valid[row];
    unsigned v = 0;
#pragma unroll
    for (int u = 0; u < 4; u++) {
        int j = t * 4 + u;
        int a = (i == j);
        if (i == 0 && j > 0) a |= (g_valid[b * NN + j] != 0);
        if (j == 0 && i > 0) a |= (vi != 0);
        v |= ((unsigned)a) << (8 * u);
    }
    ((unsigned*)(g_adj + (size_t)row * NN))[t] = v;
}

// ---------------- KNN k=3 (+ls in g==0) ----------------
__global__ void __launch_bounds__(64) k_knn(const float* __restrict__ coords) {
    int blk = blockIdx.x;
    int b = blk >> 5, g = blk & 31;
    int t = threadIdx.x;
    int nl = t >> 3, slot = t & 7;
    int i = g * 8 + nl;
    __shared__ float scx[NN], scy[NN];
    __shared__ int sval[NN];
    __shared__ float st_d[8][8][3];
    __shared__ int   st_i[8][8][3];
    __shared__ float lsS[2], lsC[2];
    for (int j = t; j < NN; j += 64) {
        scx[j] = coords[(b * NN + j) * 2 + 0];
        scy[j] = coords[(b * NN + j) * 2 + 1];
        sval[j] = g_valid[b * NN + j];
    }
    __syncthreads();
    if (g == 0) {
        float sS = 0.f, sC = 0.f;
        for (int j = t; j < NN; j += 64) {
            if (j > 0 && sval[j]) {
                sS += sqrtf(scx[j] * scx[j] + scy[j] * scy[j] + 1e-8f);
                sC += 1.f;
            }
        }
        sS = wredsum(sS); sC = wredsum(sC);
        if ((t & 31) == 0) { lsS[t >> 5] = sS; lsC[t >> 5] = sC; }
        __syncthreads();
        if (t == 0) {
            float tS = lsS[0] + lsS[1], tC = lsC[0] + lsC[1];
            float ls = tS / fmaxf(tC, 1.f);
            g_ls[b] = (ls > 0.f) ? ls : 1.f;
        }
    }
    float bd0 = FLT_MAX, bd1 = FLT_MAX, bd2 = FLT_MAX;
    int   bi0 = -1, bi1 = -1, bi2 = -1;
    int active = (i >= 1) && sval[i];
    if (active) {
        float cix = scx[i], ciy = scy[i];
        for (int j = 1 + slot; j < NN; j += 8) {
            if (j == i || !sval[j]) continue;
            float dx = scx[j] - cix, dy = scy[j] - ciy;
            float d2 = dx * dx + dy * dy;
            if (d2 < bd0)      { bd2 = bd1; bi2 = bi1; bd1 = bd0; bi1 = bi0; bd0 = d2; bi0 = j; }
            else if (d2 < bd1) { bd2 = bd1; bi2 = bi1; bd1 = d2; bi1 = j; }
            else if (d2 < bd2) { bd2 = d2; bi2 = j; }
        }
    }
    st_d[nl][slot][0] = bd0; st_i[nl][slot][0] = bi0;
    st_d[nl][slot][1] = bd1; st_i[nl][slot][1] = bi1;
    st_d[nl][slot][2] = bd2; st_i[nl][slot][2] = bi2;
    __syncthreads();
    if (slot == 0 && active) {
        float m0 = FLT_MAX, m1 = FLT_MAX, m2 = FLT_MAX;
        int   x0 = -1, x1 = -1, x2 = -1;
#pragma unroll
        for (int s = 0; s < 8; s++) {
#pragma unroll
            for (int k = 0; k < 3; k++) {
                float d = st_d[nl][s][k];
                int   x = st_i[nl][s][k];
                if (x < 0) continue;
                if (d < m0)      { m2 = m1; x2 = x1; m1 = m0; x1 = x0; m0 = d; x0 = x; }
                else if (d < m1) { m2 = m1; x2 = x1; m1 = d; x1 = x; }
                else if (d < m2) { m2 = d; x2 = x; }
            }
        }
        size_t rb = (size_t)(b * NN + i) * NN;
        if (x0 >= 0) { g_adj[rb + x0] = 1; g_adj[(size_t)(b * NN + x0) * NN + i] = 1; }
        if (x1 >= 0) { g_adj[rb + x1] = 1; g_adj[(size_t)(b * NN + x1) * NN + i] = 1; }
        if (x2 >= 0) { g_adj[rb + x2] = 1; g_adj[(size_t)(b * NN + x2) * NN + i] = 1; }
    }
}

// ---------------- edge list via ballot compaction ----------------
__global__ void __launch_bounds__(256) k_elist() {
    int row = blockIdx.x;
    int t = threadIdx.x;
    int w = t >> 5, lane = t & 31;
    __shared__ int wcnt[8], woff[8];
    __shared__ int sbase;
    int a = g_adj[(size_t)row * NN + t];
    unsigned bal = __ballot_sync(0xffffffffu, a != 0);
    if (lane == 0) wcnt[w] = __popc(bal);
    __syncthreads();
    if (t == 0) {
        int s = 0;
#pragma unroll
        for (int k = 0; k < 8; k++) { woff[k] = s; s += wcnt[k]; }
        sbase = atomicAdd(&g_ecnt, s);
    }
    __syncthreads();
    if (a) {
        int rank = woff[w] + __popc(bal & ((1u << lane) - 1u));
        int b = row >> 8, i = row & 255;
        g_elist[sbase + rank] = (b << 16) | (i << 8) | t;
    }
}

// ---------------- layernorm ----------------
__global__ void __launch_bounds__(256) k_layernorm(const float* __restrict__ x,
                            const float* __restrict__ w,
                            const float* __restrict__ bia, float* __restrict__ out) {
    int row = blockIdx.x, t = threadIdx.x;
    float v = x[(size_t)row * DD + t];
    __shared__ float s8[8];
    float ws = wredsum(v);
    if ((t & 31) == 0) s8[t >> 5] = ws;
    __syncthreads();
    float mean = 0.f;
#pragma unroll
    for (int k = 0; k < 8; k++) mean += s8[k];
    mean *= (1.f / DD);
    float d = v - mean;
    __syncthreads();
    ws = wredsum(d * d);
    if ((t & 31) == 0) s8[t >> 5] = ws;
    __syncthreads();
    float var = 0.f;
#pragma unroll
    for (int k = 0; k < 8; k++) var += s8[k];
    var *= (1.f / DD);
    out[(size_t)row * DD + t] = d * rsqrtf(var + 1e-5f) * w[t] + bia[t];
}

// ---------------- GEMM v4: f32x2, 32x64 tile, 128 threads ----------------
template<bool GLU, bool HASBIAS, bool HASRES>
__global__ void __launch_bounds__(128) k_gemm4(
    const float* __restrict__ A, const float* __restrict__ W,
    const float* __restrict__ bias, const float* __restrict__ resid,
    float* __restrict__ C,
    int K, int lda, int ldw, int ldc,
    long aStrideZ, long wStrideZ, long cStrideZ, int biasStrideZ)
{
    __shared__ float As[16][32];
    __shared__ float Ws[16][64];
    int z = blockIdx.z;
    A += (long)z * aStrideZ;
    W += (long)z * wStrideZ;
    C += (long)z * cStrideZ;
    const float* Rp = resid;
    if (HASRES) Rp += (long)z * cStrideZ;
    const float* Bp = bias;
    if (HASBIAS) Bp += (long)z * biasStrideZ;

    int bm = blockIdx.y, bn = blockIdx.x;
    int t = threadIdx.x;
    int tr = t >> 3, tc = t & 7;
    int lar = t >> 2, lak = (t & 3) * 4;
    int wkk = t >> 3, wn8 = (t & 7) * 8;

    const float* Abase = A + (size_t)(bm * 32 + lar) * lda + lak;
    const float* Wbase = W + (size_t)wkk * ldw + bn * 64 + wn8;

    ull acc[2][4];
#pragma unroll
    for (int r = 0; r < 2; r++)
#pragma unroll
        for (int c = 0; c < 4; c++) acc[r][c] = 0ull;

    float4 pa, pw0, pw1;
    {
        const float* p = Abase;
        if (GLU) {
            float4 av = *(const float4*)p;
            float4 gv = *(const float4*)(p + FFHALF);
            pa.x = av.x * gelu_f(gv.x); pa.y = av.y * gelu_f(gv.y);
            pa.z = av.z * gelu_f(gv.z); pa.w = av.w * gelu_f(gv.w);
        } else {
            pa = *(const float4*)p;
        }
        pw0 = *(const float4*)(Wbase + 0);
        pw1 = *(const float4*)(Wbase + 4);
    }

    for (int kt = 0; kt < K; kt += 16) {
        As[lak + 0][lar] = pa.x;
        As[lak + 1][lar] = pa.y;
        As[lak + 2][lar] = pa.z;
        As[lak + 3][lar] = pa.w;
        *(float4*)&Ws[wkk][wn8 + 0] = pw0;
        *(float4*)&Ws[wkk][wn8 + 4] = pw1;
        __syncthreads();
        if (kt + 16 < K) {
            const float* p = Abase + kt + 16;
            if (GLU) {
                float4 av = *(const float4*)p;
                float4 gv = *(const float4*)(p + FFHALF);
                pa.x = av.x * gelu_f(gv.x); pa.y = av.y * gelu_f(gv.y);
                pa.z = av.z * gelu_f(gv.z); pa.w = av.w * gelu_f(gv.w);
            } else {
                pa = *(const float4*)p;
            }
            const float* wp = Wbase + (size_t)(kt + 16) * ldw;
            pw0 = *(const float4*)(wp + 0);
            pw1 = *(const float4*)(wp + 4);
        }
#pragma unroll
        for (int kk = 0; kk < 16; kk++) {
            float2 a2 = *(const float2*)&As[kk][tr * 2];
            double2 q0 = *(const double2*)&Ws[kk][tc * 4];
            double2 q1 = *(const double2*)&Ws[kk][32 + tc * 4];
            ull b0 = __double_as_longlong(q0.x);
            ull b1 = __double_as_longlong(q0.y);
            ull b2 = __double_as_longlong(q1.x);
            ull b3 = __double_as_longlong(q1.y);
            ull a0 = pack_dup(a2.x), a1 = pack_dup(a2.y);
            ffma2(acc[0][0], a0, b0); ffma2(acc[0][1], a0, b1);
            ffma2(acc[0][2], a0, b2); ffma2(acc[0][3], a0, b3);
            ffma2(acc[1][0], a1, b0); ffma2(acc[1][1], a1, b1);
            ffma2(acc[1][2], a1, b2); ffma2(acc[1][3], a1, b3);
        }
        __syncthreads();
    }

    int col0 = bn * 64 + tc * 4;
    int col1 = col0 + 32;
    float4 bb0 = make_float4(0.f, 0.f, 0.f, 0.f);
    float4 bb1 = bb0;
    if (HASBIAS) {
        bb0 = *(const float4*)&Bp[col0];
        bb1 = *(const float4*)&Bp[col1];
    }
#pragma unroll
    for (int r = 0; r < 2; r++) {
        int row = bm * 32 + tr * 2 + r;
        float2 p0 = unpack2(acc[r][0]);
        float2 p1 = unpack2(acc[r][1]);
        float2 p2 = unpack2(acc[r][2]);
        float2 p3 = unpack2(acc[r][3]);
        float4 v0 = make_float4(p0.x + bb0.x, p0.y + bb0.y, p1.x + bb0.z, p1.y + bb0.w);
        float4 v1 = make_float4(p2.x + bb1.x, p2.y + bb1.y, p3.x + bb1.z, p3.y + bb1.w);
        if (HASRES) {
            float4 r0 = *(const float4*)&Rp[(size_t)row * ldc + col0];
            float4 r1 = *(const float4*)&Rp[(size_t)row * ldc + col1];
            v0.x += r0.x; v0.y += r0.y; v0.z += r0.z; v0.w += r0.w;
            v1.x += r1.x; v1.y += r1.y; v1.z += r1.z; v1.w += r1.w;
        }
        *(float4*)&C[(size_t)row * ldc + col0] = v0;
        *(float4*)&C[(size_t)row * ldc + col1] = v1;
    }
}

// ---------------- eb over edge list, BOTH layers in one launch ----------------
__global__ void k_eb_both(const float* __restrict__ coords,
                          const float* __restrict__ w1b, const float* __restrict__ b1b,
                          const float* __restrict__ w2b, const float* __restrict__ b2b) {
    int gwarp = blockIdx.x * (blockDim.x >> 5) + (threadIdx.x >> 5);
    int nwarp = gridDim.x * (blockDim.x >> 5);
    int lane = threadIdx.x & 31;
    int cnt = g_ecnt;
    int total = 2 * cnt;
    for (int e = gwarp; e < total; e += nwarp) {
        int l = (e >= cnt) ? 1 : 0;
        int gw = g_elist[e - l * cnt];
        const float* w1 = w1b + (size_t)l * 11 * INNER;
        const float* b1 = b1b + (size_t)l * INNER;
        const float* w2 = w2b + (size_t)l * INNER * HH;
        const float* b2 = b2b + (size_t)l * HH;
        int b = gw >> 16, i = (gw >> 8) & 255, j = gw & 255;
        float invls = 1.f / fmaxf(g_ls[b], 1e-6f);
        float cix = coords[(b * NN + i) * 2 + 0], ciy = coords[(b * NN + i) * 2 + 1];
        float cjx = coords[(b * NN + j) * 2 + 0], cjy = coords[(b * NN + j) * 2 + 1];
        float f[10];
        float dx = cjx - cix, dy = cjy - ciy;
        float dist = sqrtf(dx * dx + dy * dy + 1e-8f);
        f[0] = dx; f[1] = dy; f[2] = dist; f[3] = dist * invls;
        f[4] = (i == 0) ? 1.f : 0.f;
        f[5] = (j == 0) ? 1.f : 0.f;
        f[6] = (i == j) ? 1.f : 0.f;
        f[7] = ((i != 0) && (j != 0) && (i != j)) ? 1.f : 0.f;
        int hi = hop_of(i), hj = hop_of(j);
        f[8] = (hi == hj) ? 1.f : 0.f;
        f[9] = fabsf((float)(hj - hi));
        float a0 = 0, a1 = 0, a2 = 0, a3 = 0;
#pragma unroll
        for (int t = 0; t < 8; t++) {
            int m = t * 32 + lane;
            float h = b1[m];
#pragma unroll
            for (int q = 0; q < 10; q++) h += f[q] * w1[q * INNER + m];
            h = gelu_f(h);
            a0 += h * w2[m * 4 + 0];
            a1 += h * w2[m * 4 + 1];
            a2 += h * w2[m * 4 + 2];
            a3 += h * w2[m * 4 + 3];
        }
        a0 = wredsum(a0); a1 = wredsum(a1); a2 = wredsum(a2); a3 = wredsum(a3);
        if (lane == 0) {
            float* o = g_eb + (size_t)l * EBSZ + (size_t)((b * NN + i) * NN + j) * 4;
            o[0] = a0 + b2[0];
            o[1] = a1 + b2[1];
            o[2] = a2 + b2[2];
            o[3] = a3 + b2[3];
        }
    }
}

// ---------------- attention: scores + softmax + out_v ----------------
__global__ void __launch_bounds__(256) k_attn(int l) {
    int blk = blockIdx.x;
    int j = threadIdx.x;
    int i = blk & 255, h = (blk >> 8) & 3, b = blk >> 10;
    __shared__ float qs[DH];
    __shared__ float sp[NN];
    __shared__ float s8[8];
    if (j < DH) qs[j] = g_qkv[(size_t)(b * NN + i) * 768 + h * DH + j];
    __syncthreads();
    int adj = g_adj[(size_t)(b * NN + i) * NN + j];
    float sim = -FLT_MAX;
    if (adj) {
        const float* kr = g_qkv + (size_t)(b * NN + j) * 768 + 256 + h * DH;
        float d = 0.f;
#pragma unroll
        for (int t = 0; t < DH; t++) d += qs[t] * kr[t];
        sim = d * 0.125f + g_eb[(size_t)l * EBSZ + ((size_t)((b * NN + i) * NN) + j) * 4 + h];
    }
    float wm = wredmax(sim);
    if ((j & 31) == 0) s8[j >> 5] = wm;
    __syncthreads();
    float mx = s8[0];
#pragma unroll
    for (int k = 1; k < 8; k++) mx = fmaxf(mx, s8[k]);
    float ex = adj ? expf(sim - mx) : 0.f;
    __syncthreads();
    float wsum = wredsum(ex);
    if ((j & 31) == 0) s8[j >> 5] = wsum;
    __syncthreads();
    float tot = 0.f;
#pragma unroll
    for (int k = 0; k < 8; k++) tot += s8[k];
    float p = ex / tot;
    sp[j] = p;
    g_attn[((size_t)(b * HH + h) * NN + i) * NN + j] = p;
    __syncthreads();
    int d = j & 63, c0 = (j >> 6) * 64;
    float acc = 0.f;
    for (int jj = c0; jj < c0 + 64; jj++) {
        float pv = sp[jj];
        if (pv != 0.f)
            acc += pv * g_qkv[(size_t)(b * NN + jj) * 768 + 512 + h * DH + d];
    }
    __syncthreads();
    sp[j] = acc;
    __syncthreads();
    if (j < 64)
        g_tmp[(size_t)(b * NN + i) * INNER + h * DH + j] =
            sp[j] + sp[64 + j] + sp[128 + j] + sp[192 + j];
}

// ---------------- A_g with ballot-compacted neighbor list ----------------
__global__ void __launch_bounds__(256) k_Ag(const float* __restrict__ coords,
                     const float* __restrict__ w1, const float* __restrict__ b1) {
    int b = blockIdx.x >> 8, i = blockIdx.x & 255, m = threadIdx.x;
    int w = m >> 5, lane = m & 31;
    __shared__ float sa[HH][NN];
    __shared__ float scx[NN], scy[NN];
    __shared__ int slist[NN];
    __shared__ int wcnt[8], woff[8];
    __shared__ int scnt;
#pragma unroll
    for (int h = 0; h < HH; h++)
        sa[h][m] = g_attn[((size_t)(b * HH + h) * NN + i) * NN + m];
    int a = g_adj[(size_t)(b * NN + i) * NN + m];
    scx[m] = coords[(b * NN + m) * 2 + 0];
    scy[m] = coords[(b * NN + m) * 2 + 1];
    unsigned bal = __ballot_sync(0xffffffffu, a != 0);
    if (lane == 0) wcnt[w] = __popc(bal);
    __syncthreads();
    if (m == 0) {
        int s = 0;
#pragma unroll
        for (int k = 0; k < 8; k++) { woff[k] = s; s += wcnt[k]; }
        scnt = s;
    }
    __syncthreads();
    if (a) slist[woff[w] + __popc(bal & ((1u << lane) - 1u))] = m;
    __syncthreads();

    float w1r[10];
#pragma unroll
    for (int f = 0; f < 10; f++) w1r[f] = w1[f * INNER + m];
    float b1m = b1[m];
    float invls = 1.f / fmaxf(g_ls[b], 1e-6f);
    float cix = scx[i], ciy = scy[i];
    int hi = hop_of(i);
    float qic = (i == 0) ? 1.f : 0.f;
    float acc0 = 0, acc1 = 0, acc2 = 0, acc3 = 0;
    int nb = scnt;
    for (int t = 0; t < nb; t++) {
        int j = slist[t];
        float dx = scx[j] - cix, dy = scy[j] - ciy;
        float dist = sqrtf(dx * dx + dy * dy + 1e-8f);
        float kic = (j == 0) ? 1.f : 0.f;
        float ey = (i == j) ? 1.f : 0.f;
        float isnn = ((i != 0) && (j != 0) && (i != j)) ? 1.f : 0.f;
        int hj = hop_of(j);
        float hv = b1m + dx * w1r[0] + dy * w1r[1] + dist * w1r[2]
                 + (dist * invls) * w1r[3] + qic * w1r[4] + kic * w1r[5]
                 + ey * w1r[6] + isnn * w1r[7]
                 + ((hi == hj) ? 1.f : 0.f) * w1r[8]
                 + fabsf((float)(hj - hi)) * w1r[9];
        hv = gelu_f(hv);
        acc0 += sa[0][j] * hv;
        acc1 += sa[1][j] * hv;
        acc2 += sa[2][j] * hv;
        acc3 += sa[3][j] * hv;
    }
    size_t base = (size_t)(b * NN + i) * INNER + m;
    g_Ag[0 * (size_t)(BB * NN * INNER) + base] = acc0;
    g_Ag[1 * (size_t)(BB * NN * INNER) + base] = acc1;
    g_Ag[2 * (size_t)(BB * NN * INNER) + base] = acc2;
    g_Ag[3 * (size_t)(BB * NN * INNER) + base] = acc3;
}

// ---------------- host launch ----------------
extern "C" void kernel_launch(void* const* d_in, const int* in_sizes, int n_in,
                              void* d_out, int out_size) {
    const float* x      = (const float*)d_in[0];
    const float* coords = (const float*)d_in[1];
    const float* Wq     = (const float*)d_in[2];
    const float* Wk     = (const float*)d_in[3];
    const float* Wv     = (const float*)d_in[4];
    const float* ebw1   = (const float*)d_in[5];
    const float* ebb1   = (const float*)d_in[6];
    const float* ebw2   = (const float*)d_in[7];
    const float* ebb2   = (const float*)d_in[8];
    const float* evw1   = (const float*)d_in[9];
    const float* evb1   = (const float*)d_in[10];
    const float* evw2   = (const float*)d_in[11];
    const float* evb2   = (const float*)d_in[12];
    const float* Wo     = (const float*)d_in[13];
    const float* bo     = (const float*)d_in[14];
    const float* ln1w   = (const float*)d_in[15];
    const float* ln1b   = (const float*)d_in[16];
    const float* ln2w   = (const float*)d_in[17];
    const float* ln2b   = (const float*)d_in[18];
    const float* ffw1   = (const float*)d_in[19];
    const float* ffb1   = (const float*)d_in[20];
    const float* ffw2   = (const float*)d_in[21];
    const float* ffb2   = (const float*)d_in[22];

    static float *p_x = nullptr, *p_xn, *p_qkv, *p_wqkv, *p_tmp, *p_hg, *p_Ag;
    static cudaStream_t s2;
    static cudaEvent_t ev_start, ev_pack, ev_fork, ev_eb;
    if (!p_x) {
        cudaGetSymbolAddress((void**)&p_x,    g_x);
        cudaGetSymbolAddress((void**)&p_xn,   g_xn);
        cudaGetSymbolAddress((void**)&p_qkv,  g_qkv);
        cudaGetSymbolAddress((void**)&p_wqkv, g_wqkv);
        cudaGetSymbolAddress((void**)&p_tmp,  g_tmp);
        cudaGetSymbolAddress((void**)&p_hg,   g_hg);
        cudaGetSymbolAddress((void**)&p_Ag,   g_Ag);
        cudaStreamCreateWithFlags(&s2, cudaStreamNonBlocking);
        cudaEventCreateWithFlags(&ev_start, cudaEventDisableTiming);
        cudaEventCreateWithFlags(&ev_pack,  cudaEventDisableTiming);
        cudaEventCreateWithFlags(&ev_fork,  cudaEventDisableTiming);
        cudaEventCreateWithFlags(&ev_eb,    cudaEventDisableTiming);
    }

    const int ROWS = BB * NN;   // 1024

    // fork s2 off the capture-origin (default) stream
    cudaEventRecord(ev_start, 0);
    cudaStreamWaitEvent(s2, ev_start, 0);

    // s2: weight packing (independent of x/graph)
    k_pack<<<(LL * DD * 768) / 256, 256, 0, s2>>>(Wq, Wk, Wv);
    cudaEventRecord(ev_pack, s2);

    // stream 0: graph build
    k_loadx<<<ROWS, 256>>>(x);
    k_adj_fill<<<ROWS, 64>>>();
    k_knn<<<BB * 32, 64>>>(coords);
    k_elist<<<ROWS, 256>>>();
    cudaEventRecord(ev_fork, 0);

    // s2: both layers' eb, overlapping LN1/QKV below
    cudaStreamWaitEvent(s2, ev_fork, 0);
    k_eb_both<<<296, 256, 0, s2>>>(coords, ebw1, ebb1, ebw2, ebb2);
    cudaEventRecord(ev_eb, s2);

    for (int l = 0; l < LL; l++) {
        const float* evw1_l = evw1 + (size_t)l * 11 * INNER;
        const float* evb1_l = evb1 + (size_t)l * INNER;
        const float* Wo_l   = Wo   + (size_t)l * INNER * DD;
        const float* bo_l   = bo   + (size_t)l * DD;
        const float* evw2_l = evw2 + (size_t)l * INNER * INNER;
        const float* evb2_l = evb2 + (size_t)l * INNER;
        const float* ffw1_l = ffw1 + (size_t)l * DD * FFH;
        const float* ffb1_l = ffb1 + (size_t)l * FFH;
        const float* ffw2_l = ffw2 + (size_t)l * FFHALF * DD;
        const float* ffb2_l = ffb2 + (size_t)l * DD;

        k_layernorm<<<ROWS, 256>>>(p_x, ln1w + l * DD, ln1b + l * DD, p_xn);
        if (l == 0) cudaStreamWaitEvent(0, ev_pack, 0);
        k_gemm4<false, false, false><<<dim3(768 / 64, ROWS / 32, 1), 128>>>(
            p_xn, p_wqkv + (size_t)l * DD * 768, nullptr, nullptr, p_qkv,
            DD, DD, 768, 768, 0, 0, 0, 0);
        if (l == 0) cudaStreamWaitEvent(0, ev_eb, 0);
        k_attn<<<BB * HH * NN, 256>>>(l);
        k_Ag<<<BB * NN, 256>>>(coords, evw1_l, evb1_l);
        k_gemm4<false, true, true><<<dim3(1, ROWS / 32, HH), 128>>>(
            p_Ag, evw2_l, evb2_l, p_tmp, p_tmp,
            INNER, INNER, INNER, INNER,
            (long)BB * NN * INNER, 64, 64, 64);
        k_gemm4<false, true, true><<<dim3(DD / 64, ROWS / 32, 1), 128>>>(
            p_tmp, Wo_l, bo_l, p_x, p_x,
            INNER, INNER, DD, DD, 0, 0, 0, 0);
        k_layernorm<<<ROWS, 256>>>(p_x, ln2w + l * DD, ln2b + l * DD, p_xn);
        k_gemm4<false, true, false><<<dim3(FFH / 64, ROWS / 32, 1), 128>>>(
            p_xn, ffw1_l, ffb1_l, nullptr, p_hg,
            DD, DD, FFH, FFH, 0, 0, 0, 0);
        k_gemm4<true, true, true><<<dim3(DD / 64, ROWS / 32, 1), 128>>>(
            p_hg, ffw2_l, ffb2_l, p_x, p_x,
            FFHALF, FFH, DD, DD, 0, 0, 0, 0);
    }

    k_copy_out<<<ROWS, 64>>>((float*)d_out);
}

// round 10
// speedup vs baseline: 1.1358x; 1.1358x over previous
#include <cuda_runtime.h>
#include <math.h>
#include <float.h>

// Problem constants
#define BB 4
#define NN 256
#define DD 256
#define HH 4
#define DH 64
#define INNER 256
#define LL 2
#define FFH 1024
#define FFHALF 512
#define MAXE (BB*NN*16)
#define EBSZ (BB*NN*NN*HH)

typedef unsigned long long ull;

// ---------------- device scratch ----------------
__device__ float g_x   [BB*NN*DD];
__device__ float g_xn  [BB*NN*DD];
__device__ float g_qkv [BB*NN*768];
__device__ float g_wqkv[LL*DD*768];
__device__ float g_eb  [LL*EBSZ];
__device__ float g_attn[BB*HH*NN*NN];
__device__ float g_Ag  [HH*BB*NN*INNER];
__device__ float g_tmp [BB*NN*INNER];
__device__ float g_hg  [BB*NN*FFH];
__device__ unsigned char g_adj[BB*NN*NN];
__device__ int   g_valid[BB*NN];
__device__ float g_ls[BB];
__device__ int   g_elist[MAXE];
__device__ int   g_ecnt;

__device__ __forceinline__ float gelu_f(float x) {
    return 0.5f * x * (1.0f + erff(x * 0.70710678118654752440f));
}
__device__ __forceinline__ int hop_of(int n) {
    return (n == 0) ? 0 : ((n < 128) ? 1 : 2);
}
__device__ __forceinline__ float wredsum(float v) {
#pragma unroll
    for (int o = 16; o; o >>= 1) v += __shfl_xor_sync(0xffffffffu, v, o);
    return v;
}
__device__ __forceinline__ float wredmax(float v) {
#pragma unroll
    for (int o = 16; o; o >>= 1) v = fmaxf(v, __shfl_xor_sync(0xffffffffu, v, o));
    return v;
}

// ---------------- f32x2 packed FMA helpers ----------------
__device__ __forceinline__ void ffma2(ull& acc, ull a, ull b) {
    asm("fma.rn.f32x2 %0, %1, %2, %0;" : "+l"(acc) : "l"(a), "l"(b));
}
__device__ __forceinline__ ull pack_dup(float x) {
    ull r;
    asm("mov.b64 %0, {%1, %1};" : "=l"(r) : "f"(x));
    return r;
}
__device__ __forceinline__ float2 unpack2(ull v) {
    float2 f;
    asm("mov.b64 {%0, %1}, %2;" : "=f"(f.x), "=f"(f.y) : "l"(v));
    return f;
}

// ---------------- copy in + validity (fused) ----------------
__global__ void __launch_bounds__(256) k_loadx(const float* __restrict__ src) {
    int row = blockIdx.x, t = threadIdx.x;
    float v = src[(size_t)row * DD + t];
    g_x[(size_t)row * DD + t] = v;
    __shared__ float s8[8];
    float ws = wredsum(fabsf(v));
    if ((t & 31) == 0) s8[t >> 5] = ws;
    __syncthreads();
    if (t == 0) {
        float s = 0.f;
#pragma unroll
        for (int k = 0; k < 8; k++) s += s8[k];
        int n = row & 255;
        g_valid[row] = (s > 0.f) || (n == 0);
        if (row == 0) g_ecnt = 0;
    }
}

// ---------------- pack QKV weights ----------------
__global__ void k_pack(const float* __restrict__ Wq, const float* __restrict__ Wk,
                       const float* __restrict__ Wv) {
    int idx = blockIdx.x * blockDim.x + threadIdx.x;
    int l = idx / (DD * 768);
    int rem = idx % (DD * 768);
    int k = rem / 768, c = rem % 768;
    int z = c >> 8, n = c & 255;
    const float* src = (z == 0) ? Wq : ((z == 1) ? Wk : Wv);
    g_wqkv[idx] = src[(size_t)l * DD * INNER + k * INNER + n];
}

// ---------------- base adjacency fill (grid ROWS, 64 thr) ----------------
__global__ void __launch_bounds__(64) k_adj_fill() {
    int row = blockIdx.x;
    int b = row >> 8, i = row & 255;
    int t = threadIdx.x;
    int vi = g_valid[row];
    unsigned v = 0;
#pragma unroll
    for (int u = 0; u < 4; u++) {
        int j = t * 4 + u;
        int a = (i == j);
        if (i == 0 && j > 0) a |= (g_valid[b * NN + j] != 0);
        if (j == 0 && i > 0) a |= (vi != 0);
        v |= ((unsigned)a) << (8 * u);
    }
    ((unsigned*)(g_adj + (size_t)row * NN))[t] = v;
}

// ---------------- KNN k=3, 8 nodes per block, 8 slots per node (+ls in g==0) ----------------
__global__ void __launch_bounds__(64) k_knn(const float* __restrict__ coords) {
    int blk = blockIdx.x;          // BB*32 blocks
    int b = blk >> 5, g = blk & 31;
    int t = threadIdx.x;
    int nl = t >> 3, slot = t & 7;
    int i = g * 8 + nl;
    __shared__ float scx[NN], scy[NN];
    __shared__ int sval[NN];
    __shared__ float st_d[8][8][3];
    __shared__ int   st_i[8][8][3];
    __shared__ float lsS[2], lsC[2];
    for (int j = t; j < NN; j += 64) {
        scx[j] = coords[(b * NN + j) * 2 + 0];
        scy[j] = coords[(b * NN + j) * 2 + 1];
        sval[j] = g_valid[b * NN + j];
    }
    __syncthreads();
    if (g == 0) {
        float sS = 0.f, sC = 0.f;
        for (int j = t; j < NN; j += 64) {
            if (j > 0 && sval[j]) {
                sS += sqrtf(scx[j] * scx[j] + scy[j] * scy[j] + 1e-8f);
                sC += 1.f;
            }
        }
        sS = wredsum(sS); sC = wredsum(sC);
        if ((t & 31) == 0) { lsS[t >> 5] = sS; lsC[t >> 5] = sC; }
        __syncthreads();
        if (t == 0) {
            float tS = lsS[0] + lsS[1], tC = lsC[0] + lsC[1];
            float ls = tS / fmaxf(tC, 1.f);
            g_ls[b] = (ls > 0.f) ? ls : 1.f;
        }
    }
    float bd0 = FLT_MAX, bd1 = FLT_MAX, bd2 = FLT_MAX;
    int   bi0 = -1, bi1 = -1, bi2 = -1;
    int active = (i >= 1) && sval[i];
    if (active) {
        float cix = scx[i], ciy = scy[i];
        for (int j = 1 + slot; j < NN; j += 8) {
            if (j == i || !sval[j]) continue;
            float dx = scx[j] - cix, dy = scy[j] - ciy;
            float d2 = dx * dx + dy * dy;
            if (d2 < bd0)      { bd2 = bd1; bi2 = bi1; bd1 = bd0; bi1 = bi0; bd0 = d2; bi0 = j; }
            else if (d2 < bd1) { bd2 = bd1; bi2 = bi1; bd1 = d2; bi1 = j; }
            else if (d2 < bd2) { bd2 = d2; bi2 = j; }
        }
    }
    st_d[nl][slot][0] = bd0; st_i[nl][slot][0] = bi0;
    st_d[nl][slot][1] = bd1; st_i[nl][slot][1] = bi1;
    st_d[nl][slot][2] = bd2; st_i[nl][slot][2] = bi2;
    __syncthreads();
    if (slot == 0 && active) {
        float m0 = FLT_MAX, m1 = FLT_MAX, m2 = FLT_MAX;
        int   x0 = -1, x1 = -1, x2 = -1;
#pragma unroll
        for (int s = 0; s < 8; s++) {
#pragma unroll
            for (int k = 0; k < 3; k++) {
                float d = st_d[nl][s][k];
                int   x = st_i[nl][s][k];
                if (x < 0) continue;
                if (d < m0)      { m2 = m1; x2 = x1; m1 = m0; x1 = x0; m0 = d; x0 = x; }
                else if (d < m1) { m2 = m1; x2 = x1; m1 = d; x1 = x; }
                else if (d < m2) { m2 = d; x2 = x; }
            }
        }
        size_t rb = (size_t)(b * NN + i) * NN;
        if (x0 >= 0) { g_adj[rb + x0] = 1; g_adj[(size_t)(b * NN + x0) * NN + i] = 1; }
        if (x1 >= 0) { g_adj[rb + x1] = 1; g_adj[(size_t)(b * NN + x1) * NN + i] = 1; }
        if (x2 >= 0) { g_adj[rb + x2] = 1; g_adj[(size_t)(b * NN + x2) * NN + i] = 1; }
    }
}

// ---------------- edge list via ballot compaction (grid ROWS) ----------------
__global__ void __launch_bounds__(256) k_elist() {
    int row = blockIdx.x;
    int t = threadIdx.x;
    int w = t >> 5, lane = t & 31;
    __shared__ int wcnt[8], woff[8];
    __shared__ int sbase;
    int a = g_adj[(size_t)row * NN + t];
    unsigned bal = __ballot_sync(0xffffffffu, a != 0);
    if (lane == 0) wcnt[w] = __popc(bal);
    __syncthreads();
    if (t == 0) {
        int s = 0;
#pragma unroll
        for (int k = 0; k < 8; k++) { woff[k] = s; s += wcnt[k]; }
        sbase = atomicAdd(&g_ecnt, s);
    }
    __syncthreads();
    if (a) {
        int rank = woff[w] + __popc(bal & ((1u << lane) - 1u));
        int b = row >> 8, i = row & 255;
        g_elist[sbase + rank] = (b << 16) | (i << 8) | t;
    }
}

// ---------------- layernorm ----------------
__global__ void __launch_bounds__(256) k_layernorm(const float* __restrict__ x,
                            const float* __restrict__ w,
                            const float* __restrict__ bia, float* __restrict__ out) {
    int row = blockIdx.x, t = threadIdx.x;
    float v = x[(size_t)row * DD + t];
    __shared__ float s8[8];
    float ws = wredsum(v);
    if ((t & 31) == 0) s8[t >> 5] = ws;
    __syncthreads();
    float mean = 0.f;
#pragma unroll
    for (int k = 0; k < 8; k++) mean += s8[k];
    mean *= (1.f / DD);
    float d = v - mean;
    __syncthreads();
    ws = wredsum(d * d);
    if ((t & 31) == 0) s8[t >> 5] = ws;
    __syncthreads();
    float var = 0.f;
#pragma unroll
    for (int k = 0; k < 8; k++) var += s8[k];
    var *= (1.f / DD);
    out[(size_t)row * DD + t] = d * rsqrtf(var + 1e-5f) * w[t] + bia[t];
}

// ---------------- GEMM v3: f32x2 packed, 32x64 tile, 64 threads ----------------
template<bool GLU, bool HASBIAS, bool HASRES>
__global__ void __launch_bounds__(64) k_gemm3(
    const float* __restrict__ A, const float* __restrict__ W,
    const float* __restrict__ bias, const float* __restrict__ resid,
    float* __restrict__ C,
    int K, int lda, int ldw, int ldc,
    long aStrideZ, long wStrideZ, long cStrideZ, int biasStrideZ)
{
    __shared__ float As[16][32];
    __shared__ float Ws[16][64];
    int z = blockIdx.z;
    A += (long)z * aStrideZ;
    W += (long)z * wStrideZ;
    C += (long)z * cStrideZ;
    const float* Rp = resid;
    if (HASRES) Rp += (long)z * cStrideZ;
    const float* Bp = bias;
    if (HASBIAS) Bp += (long)z * biasStrideZ;

    int bm = blockIdx.y, bn = blockIdx.x;
    int t = threadIdx.x;
    int tr = t >> 3, tc = t & 7;
    int lar = t >> 1, lak = (t & 1) * 8;
    int lbk = t >> 2, lbc = (t & 3) * 16;

    const float* Abase = A + (size_t)(bm * 32 + lar) * lda + lak;
    const float* Wbase = W + (size_t)lbk * ldw + bn * 64 + lbc;

    ull acc[4][4];
#pragma unroll
    for (int r = 0; r < 4; r++)
#pragma unroll
        for (int c = 0; c < 4; c++) acc[r][c] = 0ull;

    float4 pa0, pa1, pw0, pw1, pw2, pw3;
    {
        const float* p = Abase;
        if (GLU) {
            float4 av = *(const float4*)p;
            float4 gv = *(const float4*)(p + FFHALF);
            pa0.x = av.x * gelu_f(gv.x); pa0.y = av.y * gelu_f(gv.y);
            pa0.z = av.z * gelu_f(gv.z); pa0.w = av.w * gelu_f(gv.w);
            av = *(const float4*)(p + 4);
            gv = *(const float4*)(p + 4 + FFHALF);
            pa1.x = av.x * gelu_f(gv.x); pa1.y = av.y * gelu_f(gv.y);
            pa1.z = av.z * gelu_f(gv.z); pa1.w = av.w * gelu_f(gv.w);
        } else {
            pa0 = *(const float4*)p;
            pa1 = *(const float4*)(p + 4);
        }
        pw0 = *(const float4*)(Wbase + 0);
        pw1 = *(const float4*)(Wbase + 4);
        pw2 = *(const float4*)(Wbase + 8);
        pw3 = *(const float4*)(Wbase + 12);
    }

    for (int kt = 0; kt < K; kt += 16) {
        As[lak + 0][lar] = pa0.x; As[lak + 1][lar] = pa0.y;
        As[lak + 2][lar] = pa0.z; As[lak + 3][lar] = pa0.w;
        As[lak + 4][lar] = pa1.x; As[lak + 5][lar] = pa1.y;
        As[lak + 6][lar] = pa1.z; As[lak + 7][lar] = pa1.w;
        *(float4*)&Ws[lbk][lbc + 0]  = pw0;
        *(float4*)&Ws[lbk][lbc + 4]  = pw1;
        *(float4*)&Ws[lbk][lbc + 8]  = pw2;
        *(float4*)&Ws[lbk][lbc + 12] = pw3;
        __syncthreads();
        if (kt + 16 < K) {
            const float* p = Abase + kt + 16;
            if (GLU) {
                float4 av = *(const float4*)p;
                float4 gv = *(const float4*)(p + FFHALF);
                pa0.x = av.x * gelu_f(gv.x); pa0.y = av.y * gelu_f(gv.y);
                pa0.z = av.z * gelu_f(gv.z); pa0.w = av.w * gelu_f(gv.w);
                av = *(const float4*)(p + 4);
                gv = *(const float4*)(p + 4 + FFHALF);
                pa1.x = av.x * gelu_f(gv.x); pa1.y = av.y * gelu_f(gv.y);
                pa1.z = av.z * gelu_f(gv.z); pa1.w = av.w * gelu_f(gv.w);
            } else {
                pa0 = *(const float4*)p;
                pa1 = *(const float4*)(p + 4);
            }
            const float* wp = Wbase + (size_t)(kt + 16) * ldw;
            pw0 = *(const float4*)(wp + 0);
            pw1 = *(const float4*)(wp + 4);
            pw2 = *(const float4*)(wp + 8);
            pw3 = *(const float4*)(wp + 12);
        }
#pragma unroll
        for (int kk = 0; kk < 16; kk++) {
            float4 a4 = *(const float4*)&As[kk][tr * 4];
            double2 q0 = *(const double2*)&Ws[kk][tc * 4];
            double2 q1 = *(const double2*)&Ws[kk][32 + tc * 4];
            ull b0 = __double_as_longlong(q0.x);
            ull b1 = __double_as_longlong(q0.y);
            ull b2 = __double_as_longlong(q1.x);
            ull b3 = __double_as_longlong(q1.y);
            ull a0 = pack_dup(a4.x), a1 = pack_dup(a4.y);
            ull a2 = pack_dup(a4.z), a3 = pack_dup(a4.w);
            ffma2(acc[0][0], a0, b0); ffma2(acc[0][1], a0, b1);
            ffma2(acc[0][2], a0, b2); ffma2(acc[0][3], a0, b3);
            ffma2(acc[1][0], a1, b0); ffma2(acc[1][1], a1, b1);
            ffma2(acc[1][2], a1, b2); ffma2(acc[1][3], a1, b3);
            ffma2(acc[2][0], a2, b0); ffma2(acc[2][1], a2, b1);
            ffma2(acc[2][2], a2, b2); ffma2(acc[2][3], a2, b3);
            ffma2(acc[3][0], a3, b0); ffma2(acc[3][1], a3, b1);
            ffma2(acc[3][2], a3, b2); ffma2(acc[3][3], a3, b3);
        }
        __syncthreads();
    }

    int col0 = bn * 64 + tc * 4;
    int col1 = col0 + 32;
    float4 bb0 = make_float4(0.f, 0.f, 0.f, 0.f);
    float4 bb1 = bb0;
    if (HASBIAS) {
        bb0 = *(const float4*)&Bp[col0];
        bb1 = *(const float4*)&Bp[col1];
    }
#pragma unroll
    for (int r = 0; r < 4; r++) {
        int row = bm * 32 + tr * 4 + r;
        float2 p0 = unpack2(acc[r][0]);
        float2 p1 = unpack2(acc[r][1]);
        float2 p2 = unpack2(acc[r][2]);
        float2 p3 = unpack2(acc[r][3]);
        float4 v0 = make_float4(p0.x + bb0.x, p0.y + bb0.y, p1.x + bb0.z, p1.y + bb0.w);
        float4 v1 = make_float4(p2.x + bb1.x, p2.y + bb1.y, p3.x + bb1.z, p3.y + bb1.w);
        if (HASRES) {
            float4 r0 = *(const float4*)&Rp[(size_t)row * ldc + col0];
            float4 r1 = *(const float4*)&Rp[(size_t)row * ldc + col1];
            v0.x += r0.x; v0.y += r0.y; v0.z += r0.z; v0.w += r0.w;
            v1.x += r1.x; v1.y += r1.y; v1.z += r1.z; v1.w += r1.w;
        }
        *(float4*)&C[(size_t)row * ldc + col0] = v0;
        *(float4*)&C[(size_t)row * ldc + col1] = v1;
    }
}

// ---------------- eb over edge list, BOTH layers in one launch ----------------
__global__ void k_eb_both(const float* __restrict__ coords,
                          const float* __restrict__ w1b, const float* __restrict__ b1b,
                          const float* __restrict__ w2b, const float* __restrict__ b2b) {
    int gwarp = blockIdx.x * (blockDim.x >> 5) + (threadIdx.x >> 5);
    int nwarp = gridDim.x * (blockDim.x >> 5);
    int lane = threadIdx.x & 31;
    int cnt = g_ecnt;
    int total = 2 * cnt;
    for (int e = gwarp; e < total; e += nwarp) {
        int l = (e >= cnt) ? 1 : 0;
        int gw = g_elist[e - l * cnt];
        const float* w1 = w1b + (size_t)l * 11 * INNER;
        const float* b1 = b1b + (size_t)l * INNER;
        const float* w2 = w2b + (size_t)l * INNER * HH;
        const float* b2 = b2b + (size_t)l * HH;
        int b = gw >> 16, i = (gw >> 8) & 255, j = gw & 255;
        float invls = 1.f / fmaxf(g_ls[b], 1e-6f);
        float cix = coords[(b * NN + i) * 2 + 0], ciy = coords[(b * NN + i) * 2 + 1];
        float cjx = coords[(b * NN + j) * 2 + 0], cjy = coords[(b * NN + j) * 2 + 1];
        float f[10];
        float dx = cjx - cix, dy = cjy - ciy;
        float dist = sqrtf(dx * dx + dy * dy + 1e-8f);
        f[0] = dx; f[1] = dy; f[2] = dist; f[3] = dist * invls;
        f[4] = (i == 0) ? 1.f : 0.f;
        f[5] = (j == 0) ? 1.f : 0.f;
        f[6] = (i == j) ? 1.f : 0.f;
        f[7] = ((i != 0) && (j != 0) && (i != j)) ? 1.f : 0.f;
        int hi = hop_of(i), hj = hop_of(j);
        f[8] = (hi == hj) ? 1.f : 0.f;
        f[9] = fabsf((float)(hj - hi));
        float a0 = 0, a1 = 0, a2 = 0, a3 = 0;
#pragma unroll
        for (int t = 0; t < 8; t++) {
            int m = t * 32 + lane;
            float h = b1[m];
#pragma unroll
            for (int q = 0; q < 10; q++) h += f[q] * w1[q * INNER + m];
            h = gelu_f(h);
            a0 += h * w2[m * 4 + 0];
            a1 += h * w2[m * 4 + 1];
            a2 += h * w2[m * 4 + 2];
            a3 += h * w2[m * 4 + 3];
        }
        a0 = wredsum(a0); a1 = wredsum(a1); a2 = wredsum(a2); a3 = wredsum(a3);
        if (lane == 0) {
            float* o = g_eb + (size_t)l * EBSZ + (size_t)((b * NN + i) * NN + j) * 4;
            o[0] = a0 + b2[0];
            o[1] = a1 + b2[1];
            o[2] = a2 + b2[2];
            o[3] = a3 + b2[3];
        }
    }
}

// ---------------- attention: scores + softmax + out_v ----------------
__global__ void __launch_bounds__(256) k_attn(int l) {
    int blk = blockIdx.x;
    int j = threadIdx.x;
    int i = blk & 255, h = (blk >> 8) & 3, b = blk >> 10;
    __shared__ float qs[DH];
    __shared__ float sp[NN];
    __shared__ float s8[8];
    if (j < DH) qs[j] = g_qkv[(size_t)(b * NN + i) * 768 + h * DH + j];
    __syncthreads();
    int adj = g_adj[(size_t)(b * NN + i) * NN + j];
    float sim = -FLT_MAX;
    if (adj) {
        const float* kr = g_qkv + (size_t)(b * NN + j) * 768 + 256 + h * DH;
        float d = 0.f;
#pragma unroll
        for (int t = 0; t < DH; t++) d += qs[t] * kr[t];
        sim = d * 0.125f + g_eb[(size_t)l * EBSZ + ((size_t)((b * NN + i) * NN) + j) * 4 + h];
    }
    float wm = wredmax(sim);
    if ((j & 31) == 0) s8[j >> 5] = wm;
    __syncthreads();
    float mx = s8[0];
#pragma unroll
    for (int k = 1; k < 8; k++) mx = fmaxf(mx, s8[k]);
    float ex = adj ? expf(sim - mx) : 0.f;
    __syncthreads();
    float wsum = wredsum(ex);
    if ((j & 31) == 0) s8[j >> 5] = wsum;
    __syncthreads();
    float tot = 0.f;
#pragma unroll
    for (int k = 0; k < 8; k++) tot += s8[k];
    float p = ex / tot;
    sp[j] = p;
    g_attn[((size_t)(b * HH + h) * NN + i) * NN + j] = p;
    __syncthreads();
    int d = j & 63, c0 = (j >> 6) * 64;
    float acc = 0.f;
    for (int jj = c0; jj < c0 + 64; jj++) {
        float pv = sp[jj];
        if (pv != 0.f)
            acc += pv * g_qkv[(size_t)(b * NN + jj) * 768 + 512 + h * DH + d];
    }
    __syncthreads();
    sp[j] = acc;
    __syncthreads();
    if (j < 64)
        g_tmp[(size_t)(b * NN + i) * INNER + h * DH + j] =
            sp[j] + sp[64 + j] + sp[128 + j] + sp[192 + j];
}

// ---------------- A_g with ballot-compacted neighbor list ----------------
__global__ void __launch_bounds__(256) k_Ag(const float* __restrict__ coords,
                     const float* __restrict__ w1, const float* __restrict__ b1) {
    int b = blockIdx.x >> 8, i = blockIdx.x & 255, m = threadIdx.x;
    int w = m >> 5, lane = m & 31;
    __shared__ float sa[HH][NN];
    __shared__ float scx[NN], scy[NN];
    __shared__ int slist[NN];
    __shared__ int wcnt[8], woff[8];
    __shared__ int scnt;
#pragma unroll
    for (int h = 0; h < HH; h++)
        sa[h][m] = g_attn[((size_t)(b * HH + h) * NN + i) * NN + m];
    int a = g_adj[(size_t)(b * NN + i) * NN + m];
    scx[m] = coords[(b * NN + m) * 2 + 0];
    scy[m] = coords[(b * NN + m) * 2 + 1];
    unsigned bal = __ballot_sync(0xffffffffu, a != 0);
    if (lane == 0) wcnt[w] = __popc(bal);
    __syncthreads();
    if (m == 0) {
        int s = 0;
#pragma unroll
        for (int k = 0; k < 8; k++) { woff[k] = s; s += wcnt[k]; }
        scnt = s;
    }
    __syncthreads();
    if (a) slist[woff[w] + __popc(bal & ((1u << lane) - 1u))] = m;
    __syncthreads();

    float w1r[10];
#pragma unroll
    for (int f = 0; f < 10; f++) w1r[f] = w1[f * INNER + m];
    float b1m = b1[m];
    float invls = 1.f / fmaxf(g_ls[b], 1e-6f);
    float cix = scx[i], ciy = scy[i];
    int hi = hop_of(i);
    float qic = (i == 0) ? 1.f : 0.f;
    float acc0 = 0, acc1 = 0, acc2 = 0, acc3 = 0;
    int nb = scnt;
    for (int t = 0; t < nb; t++) {
        int j = slist[t];
        float dx = scx[j] - cix, dy = scy[j] - ciy;
        float dist = sqrtf(dx * dx + dy * dy + 1e-8f);
        float kic = (j == 0) ? 1.f : 0.f;
        float ey = (i == j) ? 1.f : 0.f;
        float isnn = ((i != 0) && (j != 0) && (i != j)) ? 1.f : 0.f;
        int hj = hop_of(j);
        float hv = b1m + dx * w1r[0] + dy * w1r[1] + dist * w1r[2]
                 + (dist * invls) * w1r[3] + qic * w1r[4] + kic * w1r[5]
                 + ey * w1r[6] + isnn * w1r[7]
                 + ((hi == hj) ? 1.f : 0.f) * w1r[8]
                 + fabsf((float)(hj - hi)) * w1r[9];
        hv = gelu_f(hv);
        acc0 += sa[0][j] * hv;
        acc1 += sa[1][j] * hv;
        acc2 += sa[2][j] * hv;
        acc3 += sa[3][j] * hv;
    }
    size_t base = (size_t)(b * NN + i) * INNER + m;
    g_Ag[0 * (size_t)(BB * NN * INNER) + base] = acc0;
    g_Ag[1 * (size_t)(BB * NN * INNER) + base] = acc1;
    g_Ag[2 * (size_t)(BB * NN * INNER) + base] = acc2;
    g_Ag[3 * (size_t)(BB * NN * INNER) + base] = acc3;
}

// ---------------- host launch ----------------
extern "C" void kernel_launch(void* const* d_in, const int* in_sizes, int n_in,
                              void* d_out, int out_size) {
    const float* x      = (const float*)d_in[0];
    const float* coords = (const float*)d_in[1];
    const float* Wq     = (const float*)d_in[2];
    const float* Wk     = (const float*)d_in[3];
    const float* Wv     = (const float*)d_in[4];
    const float* ebw1   = (const float*)d_in[5];
    const float* ebb1   = (const float*)d_in[6];
    const float* ebw2   = (const float*)d_in[7];
    const float* ebb2   = (const float*)d_in[8];
    const float* evw1   = (const float*)d_in[9];
    const float* evb1   = (const float*)d_in[10];
    const float* evw2   = (const float*)d_in[11];
    const float* evb2   = (const float*)d_in[12];
    const float* Wo     = (const float*)d_in[13];
    const float* bo     = (const float*)d_in[14];
    const float* ln1w   = (const float*)d_in[15];
    const float* ln1b   = (const float*)d_in[16];
    const float* ln2w   = (const float*)d_in[17];
    const float* ln2b   = (const float*)d_in[18];
    const float* ffw1   = (const float*)d_in[19];
    const float* ffb1   = (const float*)d_in[20];
    const float* ffw2   = (const float*)d_in[21];
    const float* ffb2   = (const float*)d_in[22];

    static float *p_x = nullptr, *p_xn, *p_qkv, *p_wqkv, *p_tmp, *p_hg, *p_Ag;
    if (!p_x) {
        cudaGetSymbolAddress((void**)&p_x,    g_x);
        cudaGetSymbolAddress((void**)&p_xn,   g_xn);
        cudaGetSymbolAddress((void**)&p_qkv,  g_qkv);
        cudaGetSymbolAddress((void**)&p_wqkv, g_wqkv);
        cudaGetSymbolAddress((void**)&p_tmp,  g_tmp);
        cudaGetSymbolAddress((void**)&p_hg,   g_hg);
        cudaGetSymbolAddress((void**)&p_Ag,   g_Ag);
    }

    const int ROWS = BB * NN;   // 1024

    k_loadx<<<ROWS, 256>>>(x);
    k_pack<<<(LL * DD * 768) / 256, 256>>>(Wq, Wk, Wv);
    k_adj_fill<<<ROWS, 64>>>();
    k_knn<<<BB * 32, 64>>>(coords);
    k_elist<<<ROWS, 256>>>();
    k_eb_both<<<296, 256>>>(coords, ebw1, ebb1, ebw2, ebb2);

    for (int l = 0; l < LL; l++) {
        const float* evw1_l = evw1 + (size_t)l * 11 * INNER;
        const float* evb1_l = evb1 + (size_t)l * INNER;
        const float* Wo_l   = Wo   + (size_t)l * INNER * DD;
        const float* bo_l   = bo   + (size_t)l * DD;
        const float* evw2_l = evw2 + (size_t)l * INNER * INNER;
        const float* evb2_l = evb2 + (size_t)l * INNER;
        const float* ffw1_l = ffw1 + (size_t)l * DD * FFH;
        const float* ffb1_l = ffb1 + (size_t)l * FFH;
        const float* ffw2_l = ffw2 + (size_t)l * FFHALF * DD;
        const float* ffb2_l = ffb2 + (size_t)l * DD;

        k_layernorm<<<ROWS, 256>>>(p_x, ln1w + l * DD, ln1b + l * DD, p_xn);
        k_gemm3<false, false, false><<<dim3(768 / 64, ROWS / 32, 1), 64>>>(
            p_xn, p_wqkv + (size_t)l * DD * 768, nullptr, nullptr, p_qkv,
            DD, DD, 768, 768, 0, 0, 0, 0);
        k_attn<<<BB * HH * NN, 256>>>(l);
        k_Ag<<<BB * NN, 256>>>(coords, evw1_l, evb1_l);
        k_gemm3<false, true, true><<<dim3(1, ROWS / 32, HH), 64>>>(
            p_Ag, evw2_l, evb2_l, p_tmp, p_tmp,
            INNER, INNER, INNER, INNER,
            (long)BB * NN * INNER, 64, 64, 64);
        k_gemm3<false, true, true><<<dim3(DD / 64, ROWS / 32, 1), 64>>>(
            p_tmp, Wo_l, bo_l, p_x, p_x,
            INNER, INNER, DD, DD, 0, 0, 0, 0);
        k_layernorm<<<ROWS, 256>>>(p_x, ln2w + l * DD, ln2b + l * DD, p_xn);
        k_gemm3<false, true, false><<<dim3(FFH / 64, ROWS / 32, 1), 64>>>(
            p_xn, ffw1_l, ffb1_l, nullptr, p_hg,
            DD, DD, FFH, FFH, 0, 0, 0, 0);
        // last layer: write final x straight to d_out (x = resid + glu@W2)
        float* outC = (l == LL - 1) ? (float*)d_out : p_x;
        k_gemm3<true, true, true><<<dim3(DD / 64, ROWS / 32, 1), 64>>>(
            p_hg, ffw2_l, ffb2_l, p_x, outC,
            FFHALF, FFH, DD, DD, 0, 0, 0, 0);
    }
}

// round 11
// speedup vs baseline: 1.1830x; 1.0416x over previous
#include <cuda_runtime.h>
#include <math.h>
#include <float.h>

// Problem constants
#define BB 4
#define NN 256
#define DD 256
#define HH 4
#define DH 64
#define INNER 256
#define LL 2
#define FFH 1024
#define FFHALF 512
#define MAXE (BB*NN*16)
#define EBSZ (BB*NN*NN*HH)

typedef unsigned long long ull;

// ---------------- device scratch ----------------
__device__ float g_x   [BB*NN*DD];
__device__ float g_xn  [BB*NN*DD];
__device__ float g_qkv [BB*NN*768];
__device__ float g_wqkv[LL*DD*768];
__device__ float g_eb  [LL*EBSZ];
__device__ float g_attn[BB*HH*NN*NN];        // compact probs: [bh][i][n<deg]
__device__ float g_Ag  [HH*BB*NN*INNER];
__device__ float g_tmp [BB*NN*INNER];
__device__ float g_hg  [BB*NN*FFH];
__device__ unsigned char g_adj[BB*NN*NN];
__device__ int   g_valid[BB*NN];
__device__ float g_ls[BB];
__device__ int   g_elist[MAXE];
__device__ int   g_ecnt;

__device__ __forceinline__ float gelu_f(float x) {
    return 0.5f * x * (1.0f + erff(x * 0.70710678118654752440f));
}
__device__ __forceinline__ int hop_of(int n) {
    return (n == 0) ? 0 : ((n < 128) ? 1 : 2);
}
__device__ __forceinline__ float wredsum(float v) {
#pragma unroll
    for (int o = 16; o; o >>= 1) v += __shfl_xor_sync(0xffffffffu, v, o);
    return v;
}
__device__ __forceinline__ float wredmax(float v) {
#pragma unroll
    for (int o = 16; o; o >>= 1) v = fmaxf(v, __shfl_xor_sync(0xffffffffu, v, o));
    return v;
}

// ---------------- f32x2 packed FMA helpers ----------------
__device__ __forceinline__ void ffma2(ull& acc, ull a, ull b) {
    asm("fma.rn.f32x2 %0, %1, %2, %0;" : "+l"(acc) : "l"(a), "l"(b));
}
__device__ __forceinline__ ull pack_dup(float x) {
    ull r;
    asm("mov.b64 %0, {%1, %1};" : "=l"(r) : "f"(x));
    return r;
}
__device__ __forceinline__ float2 unpack2(ull v) {
    float2 f;
    asm("mov.b64 {%0, %1}, %2;" : "=f"(f.x), "=f"(f.y) : "l"(v));
    return f;
}

// ---------------- copy in + validity (fused) ----------------
__global__ void __launch_bounds__(256) k_loadx(const float* __restrict__ src) {
    int row = blockIdx.x, t = threadIdx.x;
    float v = src[(size_t)row * DD + t];
    g_x[(size_t)row * DD + t] = v;
    __shared__ float s8[8];
    float ws = wredsum(fabsf(v));
    if ((t & 31) == 0) s8[t >> 5] = ws;
    __syncthreads();
    if (t == 0) {
        float s = 0.f;
#pragma unroll
        for (int k = 0; k < 8; k++) s += s8[k];
        int n = row & 255;
        g_valid[row] = (s > 0.f) || (n == 0);
        if (row == 0) g_ecnt = 0;
    }
}

// ---------------- pack QKV weights ----------------
__global__ void k_pack(const float* __restrict__ Wq, const float* __restrict__ Wk,
                       const float* __restrict__ Wv) {
    int idx = blockIdx.x * blockDim.x + threadIdx.x;
    int l = idx / (DD * 768);
    int rem = idx % (DD * 768);
    int k = rem / 768, c = rem % 768;
    int z = c >> 8, n = c & 255;
    const float* src = (z == 0) ? Wq : ((z == 1) ? Wk : Wv);
    g_wqkv[idx] = src[(size_t)l * DD * INNER + k * INNER + n];
}

// ---------------- base adjacency fill ----------------
__global__ void __launch_bounds__(64) k_adj_fill() {
    int row = blockIdx.x;
    int b = row >> 8, i = row & 255;
    int t = threadIdx.x;
    int vi = g_valid[row];
    unsigned v = 0;
#pragma unroll
    for (int u = 0; u < 4; u++) {
        int j = t * 4 + u;
        int a = (i == j);
        if (i == 0 && j > 0) a |= (g_valid[b * NN + j] != 0);
        if (j == 0 && i > 0) a |= (vi != 0);
        v |= ((unsigned)a) << (8 * u);
    }
    ((unsigned*)(g_adj + (size_t)row * NN))[t] = v;
}

// ---------------- KNN k=3 (+ls in g==0) ----------------
__global__ void __launch_bounds__(64) k_knn(const float* __restrict__ coords) {
    int blk = blockIdx.x;
    int b = blk >> 5, g = blk & 31;
    int t = threadIdx.x;
    int nl = t >> 3, slot = t & 7;
    int i = g * 8 + nl;
    __shared__ float scx[NN], scy[NN];
    __shared__ int sval[NN];
    __shared__ float st_d[8][8][3];
    __shared__ int   st_i[8][8][3];
    __shared__ float lsS[2], lsC[2];
    for (int j = t; j < NN; j += 64) {
        scx[j] = coords[(b * NN + j) * 2 + 0];
        scy[j] = coords[(b * NN + j) * 2 + 1];
        sval[j] = g_valid[b * NN + j];
    }
    __syncthreads();
    if (g == 0) {
        float sS = 0.f, sC = 0.f;
        for (int j = t; j < NN; j += 64) {
            if (j > 0 && sval[j]) {
                sS += sqrtf(scx[j] * scx[j] + scy[j] * scy[j] + 1e-8f);
                sC += 1.f;
            }
        }
        sS = wredsum(sS); sC = wredsum(sC);
        if ((t & 31) == 0) { lsS[t >> 5] = sS; lsC[t >> 5] = sC; }
        __syncthreads();
        if (t == 0) {
            float tS = lsS[0] + lsS[1], tC = lsC[0] + lsC[1];
            float ls = tS / fmaxf(tC, 1.f);
            g_ls[b] = (ls > 0.f) ? ls : 1.f;
        }
    }
    float bd0 = FLT_MAX, bd1 = FLT_MAX, bd2 = FLT_MAX;
    int   bi0 = -1, bi1 = -1, bi2 = -1;
    int active = (i >= 1) && sval[i];
    if (active) {
        float cix = scx[i], ciy = scy[i];
        for (int j = 1 + slot; j < NN; j += 8) {
            if (j == i || !sval[j]) continue;
            float dx = scx[j] - cix, dy = scy[j] - ciy;
            float d2 = dx * dx + dy * dy;
            if (d2 < bd0)      { bd2 = bd1; bi2 = bi1; bd1 = bd0; bi1 = bi0; bd0 = d2; bi0 = j; }
            else if (d2 < bd1) { bd2 = bd1; bi2 = bi1; bd1 = d2; bi1 = j; }
            else if (d2 < bd2) { bd2 = d2; bi2 = j; }
        }
    }
    st_d[nl][slot][0] = bd0; st_i[nl][slot][0] = bi0;
    st_d[nl][slot][1] = bd1; st_i[nl][slot][1] = bi1;
    st_d[nl][slot][2] = bd2; st_i[nl][slot][2] = bi2;
    __syncthreads();
    if (slot == 0 && active) {
        float m0 = FLT_MAX, m1 = FLT_MAX, m2 = FLT_MAX;
        int   x0 = -1, x1 = -1, x2 = -1;
#pragma unroll
        for (int s = 0; s < 8; s++) {
#pragma unroll
            for (int k = 0; k < 3; k++) {
                float d = st_d[nl][s][k];
                int   x = st_i[nl][s][k];
                if (x < 0) continue;
                if (d < m0)      { m2 = m1; x2 = x1; m1 = m0; x1 = x0; m0 = d; x0 = x; }
                else if (d < m1) { m2 = m1; x2 = x1; m1 = d; x1 = x; }
                else if (d < m2) { m2 = d; x2 = x; }
            }
        }
        size_t rb = (size_t)(b * NN + i) * NN;
        if (x0 >= 0) { g_adj[rb + x0] = 1; g_adj[(size_t)(b * NN + x0) * NN + i] = 1; }
        if (x1 >= 0) { g_adj[rb + x1] = 1; g_adj[(size_t)(b * NN + x1) * NN + i] = 1; }
        if (x2 >= 0) { g_adj[rb + x2] = 1; g_adj[(size_t)(b * NN + x2) * NN + i] = 1; }
    }
}

// ---------------- edge list via ballot compaction ----------------
__global__ void __launch_bounds__(256) k_elist() {
    int row = blockIdx.x;
    int t = threadIdx.x;
    int w = t >> 5, lane = t & 31;
    __shared__ int wcnt[8], woff[8];
    __shared__ int sbase;
    int a = g_adj[(size_t)row * NN + t];
    unsigned bal = __ballot_sync(0xffffffffu, a != 0);
    if (lane == 0) wcnt[w] = __popc(bal);
    __syncthreads();
    if (t == 0) {
        int s = 0;
#pragma unroll
        for (int k = 0; k < 8; k++) { woff[k] = s; s += wcnt[k]; }
        sbase = atomicAdd(&g_ecnt, s);
    }
    __syncthreads();
    if (a) {
        int rank = woff[w] + __popc(bal & ((1u << lane) - 1u));
        int b = row >> 8, i = row & 255;
        g_elist[sbase + rank] = (b << 16) | (i << 8) | t;
    }
}

// ---------------- layernorm ----------------
__global__ void __launch_bounds__(256) k_layernorm(const float* __restrict__ x,
                            const float* __restrict__ w,
                            const float* __restrict__ bia, float* __restrict__ out) {
    int row = blockIdx.x, t = threadIdx.x;
    float v = x[(size_t)row * DD + t];
    __shared__ float s8[8];
    float ws = wredsum(v);
    if ((t & 31) == 0) s8[t >> 5] = ws;
    __syncthreads();
    float mean = 0.f;
#pragma unroll
    for (int k = 0; k < 8; k++) mean += s8[k];
    mean *= (1.f / DD);
    float d = v - mean;
    __syncthreads();
    ws = wredsum(d * d);
    if ((t & 31) == 0) s8[t >> 5] = ws;
    __syncthreads();
    float var = 0.f;
#pragma unroll
    for (int k = 0; k < 8; k++) var += s8[k];
    var *= (1.f / DD);
    out[(size_t)row * DD + t] = d * rsqrtf(var + 1e-5f) * w[t] + bia[t];
}

// ---------------- GEMM v3: f32x2 packed, 32x64 tile, 64 threads ----------------
template<bool GLU, bool HASBIAS, bool HASRES>
__global__ void __launch_bounds__(64) k_gemm3(
    const float* __restrict__ A, const float* __restrict__ W,
    const float* __restrict__ bias, const float* __restrict__ resid,
    float* __restrict__ C,
    int K, int lda, int ldw, int ldc,
    long aStrideZ, long wStrideZ, long cStrideZ, int biasStrideZ)
{
    __shared__ float As[16][32];
    __shared__ float Ws[16][64];
    int z = blockIdx.z;
    A += (long)z * aStrideZ;
    W += (long)z * wStrideZ;
    C += (long)z * cStrideZ;
    const float* Rp = resid;
    if (HASRES) Rp += (long)z * cStrideZ;
    const float* Bp = bias;
    if (HASBIAS) Bp += (long)z * biasStrideZ;

    int bm = blockIdx.y, bn = blockIdx.x;
    int t = threadIdx.x;
    int tr = t >> 3, tc = t & 7;
    int lar = t >> 1, lak = (t & 1) * 8;
    int lbk = t >> 2, lbc = (t & 3) * 16;

    const float* Abase = A + (size_t)(bm * 32 + lar) * lda + lak;
    const float* Wbase = W + (size_t)lbk * ldw + bn * 64 + lbc;

    ull acc[4][4];
#pragma unroll
    for (int r = 0; r < 4; r++)
#pragma unroll
        for (int c = 0; c < 4; c++) acc[r][c] = 0ull;

    float4 pa0, pa1, pw0, pw1, pw2, pw3;
    {
        const float* p = Abase;
        if (GLU) {
            float4 av = *(const float4*)p;
            float4 gv = *(const float4*)(p + FFHALF);
            pa0.x = av.x * gelu_f(gv.x); pa0.y = av.y * gelu_f(gv.y);
            pa0.z = av.z * gelu_f(gv.z); pa0.w = av.w * gelu_f(gv.w);
            av = *(const float4*)(p + 4);
            gv = *(const float4*)(p + 4 + FFHALF);
            pa1.x = av.x * gelu_f(gv.x); pa1.y = av.y * gelu_f(gv.y);
            pa1.z = av.z * gelu_f(gv.z); pa1.w = av.w * gelu_f(gv.w);
        } else {
            pa0 = *(const float4*)p;
            pa1 = *(const float4*)(p + 4);
        }
        pw0 = *(const float4*)(Wbase + 0);
        pw1 = *(const float4*)(Wbase + 4);
        pw2 = *(const float4*)(Wbase + 8);
        pw3 = *(const float4*)(Wbase + 12);
    }

    for (int kt = 0; kt < K; kt += 16) {
        As[lak + 0][lar] = pa0.x; As[lak + 1][lar] = pa0.y;
        As[lak + 2][lar] = pa0.z; As[lak + 3][lar] = pa0.w;
        As[lak + 4][lar] = pa1.x; As[lak + 5][lar] = pa1.y;
        As[lak + 6][lar] = pa1.z; As[lak + 7][lar] = pa1.w;
        *(float4*)&Ws[lbk][lbc + 0]  = pw0;
        *(float4*)&Ws[lbk][lbc + 4]  = pw1;
        *(float4*)&Ws[lbk][lbc + 8]  = pw2;
        *(float4*)&Ws[lbk][lbc + 12] = pw3;
        __syncthreads();
        if (kt + 16 < K) {
            const float* p = Abase + kt + 16;
            if (GLU) {
                float4 av = *(const float4*)p;
                float4 gv = *(const float4*)(p + FFHALF);
                pa0.x = av.x * gelu_f(gv.x); pa0.y = av.y * gelu_f(gv.y);
                pa0.z = av.z * gelu_f(gv.z); pa0.w = av.w * gelu_f(gv.w);
                av = *(const float4*)(p + 4);
                gv = *(const float4*)(p + 4 + FFHALF);
                pa1.x = av.x * gelu_f(gv.x); pa1.y = av.y * gelu_f(gv.y);
                pa1.z = av.z * gelu_f(gv.z); pa1.w = av.w * gelu_f(gv.w);
            } else {
                pa0 = *(const float4*)p;
                pa1 = *(const float4*)(p + 4);
            }
            const float* wp = Wbase + (size_t)(kt + 16) * ldw;
            pw0 = *(const float4*)(wp + 0);
            pw1 = *(const float4*)(wp + 4);
            pw2 = *(const float4*)(wp + 8);
            pw3 = *(const float4*)(wp + 12);
        }
#pragma unroll
        for (int kk = 0; kk < 16; kk++) {
            float4 a4 = *(const float4*)&As[kk][tr * 4];
            double2 q0 = *(const double2*)&Ws[kk][tc * 4];
            double2 q1 = *(const double2*)&Ws[kk][32 + tc * 4];
            ull b0 = __double_as_longlong(q0.x);
            ull b1 = __double_as_longlong(q0.y);
            ull b2 = __double_as_longlong(q1.x);
            ull b3 = __double_as_longlong(q1.y);
            ull a0 = pack_dup(a4.x), a1 = pack_dup(a4.y);
            ull a2 = pack_dup(a4.z), a3 = pack_dup(a4.w);
            ffma2(acc[0][0], a0, b0); ffma2(acc[0][1], a0, b1);
            ffma2(acc[0][2], a0, b2); ffma2(acc[0][3], a0, b3);
            ffma2(acc[1][0], a1, b0); ffma2(acc[1][1], a1, b1);
            ffma2(acc[1][2], a1, b2); ffma2(acc[1][3], a1, b3);
            ffma2(acc[2][0], a2, b0); ffma2(acc[2][1], a2, b1);
            ffma2(acc[2][2], a2, b2); ffma2(acc[2][3], a2, b3);
            ffma2(acc[3][0], a3, b0); ffma2(acc[3][1], a3, b1);
            ffma2(acc[3][2], a3, b2); ffma2(acc[3][3], a3, b3);
        }
        __syncthreads();
    }

    int col0 = bn * 64 + tc * 4;
    int col1 = col0 + 32;
    float4 bb0 = make_float4(0.f, 0.f, 0.f, 0.f);
    float4 bb1 = bb0;
    if (HASBIAS) {
        bb0 = *(const float4*)&Bp[col0];
        bb1 = *(const float4*)&Bp[col1];
    }
#pragma unroll
    for (int r = 0; r < 4; r++) {
        int row = bm * 32 + tr * 4 + r;
        float2 p0 = unpack2(acc[r][0]);
        float2 p1 = unpack2(acc[r][1]);
        float2 p2 = unpack2(acc[r][2]);
        float2 p3 = unpack2(acc[r][3]);
        float4 v0 = make_float4(p0.x + bb0.x, p0.y + bb0.y, p1.x + bb0.z, p1.y + bb0.w);
        float4 v1 = make_float4(p2.x + bb1.x, p2.y + bb1.y, p3.x + bb1.z, p3.y + bb1.w);
        if (HASRES) {
            float4 r0 = *(const float4*)&Rp[(size_t)row * ldc + col0];
            float4 r1 = *(const float4*)&Rp[(size_t)row * ldc + col1];
            v0.x += r0.x; v0.y += r0.y; v0.z += r0.z; v0.w += r0.w;
            v1.x += r1.x; v1.y += r1.y; v1.z += r1.z; v1.w += r1.w;
        }
        *(float4*)&C[(size_t)row * ldc + col0] = v0;
        *(float4*)&C[(size_t)row * ldc + col1] = v1;
    }
}

// ---------------- eb over edge list, BOTH layers in one launch ----------------
__global__ void k_eb_both(const float* __restrict__ coords,
                          const float* __restrict__ w1b, const float* __restrict__ b1b,
                          const float* __restrict__ w2b, const float* __restrict__ b2b) {
    int gwarp = blockIdx.x * (blockDim.x >> 5) + (threadIdx.x >> 5);
    int nwarp = gridDim.x * (blockDim.x >> 5);
    int lane = threadIdx.x & 31;
    int cnt = g_ecnt;
    int total = 2 * cnt;
    for (int e = gwarp; e < total; e += nwarp) {
        int l = (e >= cnt) ? 1 : 0;
        int gw = g_elist[e - l * cnt];
        const float* w1 = w1b + (size_t)l * 11 * INNER;
        const float* b1 = b1b + (size_t)l * INNER;
        const float* w2 = w2b + (size_t)l * INNER * HH;
        const float* b2 = b2b + (size_t)l * HH;
        int b = gw >> 16, i = (gw >> 8) & 255, j = gw & 255;
        float invls = 1.f / fmaxf(g_ls[b], 1e-6f);
        float cix = coords[(b * NN + i) * 2 + 0], ciy = coords[(b * NN + i) * 2 + 1];
        float cjx = coords[(b * NN + j) * 2 + 0], cjy = coords[(b * NN + j) * 2 + 1];
        float f[10];
        float dx = cjx - cix, dy = cjy - ciy;
        float dist = sqrtf(dx * dx + dy * dy + 1e-8f);
        f[0] = dx; f[1] = dy; f[2] = dist; f[3] = dist * invls;
        f[4] = (i == 0) ? 1.f : 0.f;
        f[5] = (j == 0) ? 1.f : 0.f;
        f[6] = (i == j) ? 1.f : 0.f;
        f[7] = ((i != 0) && (j != 0) && (i != j)) ? 1.f : 0.f;
        int hi = hop_of(i), hj = hop_of(j);
        f[8] = (hi == hj) ? 1.f : 0.f;
        f[9] = fabsf((float)(hj - hi));
        float a0 = 0, a1 = 0, a2 = 0, a3 = 0;
#pragma unroll
        for (int t = 0; t < 8; t++) {
            int m = t * 32 + lane;
            float h = b1[m];
#pragma unroll
            for (int q = 0; q < 10; q++) h += f[q] * w1[q * INNER + m];
            h = gelu_f(h);
            a0 += h * w2[m * 4 + 0];
            a1 += h * w2[m * 4 + 1];
            a2 += h * w2[m * 4 + 2];
            a3 += h * w2[m * 4 + 3];
        }
        a0 = wredsum(a0); a1 = wredsum(a1); a2 = wredsum(a2); a3 = wredsum(a3);
        if (lane == 0) {
            float* o = g_eb + (size_t)l * EBSZ + (size_t)((b * NN + i) * NN + j) * 4;
            o[0] = a0 + b2[0];
            o[1] = a1 + b2[1];
            o[2] = a2 + b2[2];
            o[3] = a3 + b2[3];
        }
    }
}

// ---------------- attention (compact): scores + softmax + out_v ----------------
__global__ void __launch_bounds__(256) k_attn(int l) {
    int blk = blockIdx.x;
    int t = threadIdx.x;
    int i = blk & 255, h = (blk >> 8) & 3, b = blk >> 10;
    int w = t >> 5, lane = t & 31;
    __shared__ float qs[DH];
    __shared__ float spc[NN];     // compact probs
    __shared__ float red[NN];     // outv partials
    __shared__ int slist[NN];
    __shared__ float s8[8];
    __shared__ int wcnt[8], woff[8];
    __shared__ int scnt;
    if (t < DH) qs[t] = g_qkv[(size_t)(b * NN + i) * 768 + h * DH + t];
    int a = g_adj[(size_t)(b * NN + i) * NN + t];
    unsigned bal = __ballot_sync(0xffffffffu, a != 0);
    if (lane == 0) wcnt[w] = __popc(bal);
    __syncthreads();
    if (t == 0) {
        int s = 0;
#pragma unroll
        for (int k = 0; k < 8; k++) { woff[k] = s; s += wcnt[k]; }
        scnt = s;
    }
    __syncthreads();
    if (a) slist[woff[w] + __popc(bal & ((1u << lane) - 1u))] = t;
    __syncthreads();
    int deg = scnt;

    // sims: thread t handles compact neighbor t
    float sim = -FLT_MAX;
    if (t < deg) {
        int j = slist[t];
        const float* kr = g_qkv + (size_t)(b * NN + j) * 768 + 256 + h * DH;
        float d = 0.f;
#pragma unroll
        for (int q = 0; q < DH; q++) d += qs[q] * kr[q];
        sim = d * 0.125f + g_eb[(size_t)l * EBSZ + ((size_t)((b * NN + i) * NN) + j) * 4 + h];
    }
    float wm = wredmax(sim);
    if (lane == 0) s8[w] = wm;
    __syncthreads();
    float mx = s8[0];
#pragma unroll
    for (int k = 1; k < 8; k++) mx = fmaxf(mx, s8[k]);
    float ex = (t < deg) ? expf(sim - mx) : 0.f;
    __syncthreads();
    float wsum = wredsum(ex);
    if (lane == 0) s8[w] = wsum;
    __syncthreads();
    float tot = 0.f;
#pragma unroll
    for (int k = 0; k < 8; k++) tot += s8[k];
    if (t < deg) {
        float p = ex / tot;
        spc[t] = p;
        g_attn[((size_t)(b * HH + h) * NN + i) * NN + t] = p;  // compact store
    }
    __syncthreads();

    // out_v over compact list, 4-way split across quarters
    int d = t & 63, q4 = t >> 6;
    int per = (deg + 3) >> 2;
    int n0 = q4 * per;
    int n1 = n0 + per; if (n1 > deg) n1 = deg;
    float acc = 0.f;
    for (int n = n0; n < n1; n++)
        acc += spc[n] * g_qkv[(size_t)(b * NN + slist[n]) * 768 + 512 + h * DH + d];
    red[t] = acc;
    __syncthreads();
    if (t < 64)
        g_tmp[(size_t)(b * NN + i) * INNER + h * DH + t] =
            red[t] + red[64 + t] + red[128 + t] + red[192 + t];
}

// ---------------- A_g with compact probs ----------------
__global__ void __launch_bounds__(256) k_Ag(const float* __restrict__ coords,
                     const float* __restrict__ w1, const float* __restrict__ b1) {
    int b = blockIdx.x >> 8, i = blockIdx.x & 255, m = threadIdx.x;
    int w = m >> 5, lane = m & 31;
    __shared__ float sa[HH][NN];   // compact probs per head
    __shared__ float scx[NN], scy[NN];
    __shared__ int slist[NN];
    __shared__ int wcnt[8], woff[8];
    __shared__ int scnt;
#pragma unroll
    for (int h = 0; h < HH; h++)
        sa[h][m] = g_attn[((size_t)(b * HH + h) * NN + i) * NN + m];
    int a = g_adj[(size_t)(b * NN + i) * NN + m];
    scx[m] = coords[(b * NN + m) * 2 + 0];
    scy[m] = coords[(b * NN + m) * 2 + 1];
    unsigned bal = __ballot_sync(0xffffffffu, a != 0);
    if (lane == 0) wcnt[w] = __popc(bal);
    __syncthreads();
    if (m == 0) {
        int s = 0;
#pragma unroll
        for (int k = 0; k < 8; k++) { woff[k] = s; s += wcnt[k]; }
        scnt = s;
    }
    __syncthreads();
    if (a) slist[woff[w] + __popc(bal & ((1u << lane) - 1u))] = m;
    __syncthreads();

    float w1r[10];
#pragma unroll
    for (int f = 0; f < 10; f++) w1r[f] = w1[f * INNER + m];
    float b1m = b1[m];
    float invls = 1.f / fmaxf(g_ls[b], 1e-6f);
    float cix = scx[i], ciy = scy[i];
    int hi = hop_of(i);
    float qic = (i == 0) ? 1.f : 0.f;
    float acc0 = 0, acc1 = 0, acc2 = 0, acc3 = 0;
    int nb = scnt;
    for (int t = 0; t < nb; t++) {
        int j = slist[t];
        float dx = scx[j] - cix, dy = scy[j] - ciy;
        float dist = sqrtf(dx * dx + dy * dy + 1e-8f);
        float kic = (j == 0) ? 1.f : 0.f;
        float ey = (i == j) ? 1.f : 0.f;
        float isnn = ((i != 0) && (j != 0) && (i != j)) ? 1.f : 0.f;
        int hj = hop_of(j);
        float hv = b1m + dx * w1r[0] + dy * w1r[1] + dist * w1r[2]
                 + (dist * invls) * w1r[3] + qic * w1r[4] + kic * w1r[5]
                 + ey * w1r[6] + isnn * w1r[7]
                 + ((hi == hj) ? 1.f : 0.f) * w1r[8]
                 + fabsf((float)(hj - hi)) * w1r[9];
        hv = gelu_f(hv);
        acc0 += sa[0][t] * hv;   // compact index
        acc1 += sa[1][t] * hv;
        acc2 += sa[2][t] * hv;
        acc3 += sa[3][t] * hv;
    }
    size_t base = (size_t)(b * NN + i) * INNER + m;
    g_Ag[0 * (size_t)(BB * NN * INNER) + base] = acc0;
    g_Ag[1 * (size_t)(BB * NN * INNER) + base] = acc1;
    g_Ag[2 * (size_t)(BB * NN * INNER) + base] = acc2;
    g_Ag[3 * (size_t)(BB * NN * INNER) + base] = acc3;
}

// ---------------- host launch ----------------
extern "C" void kernel_launch(void* const* d_in, const int* in_sizes, int n_in,
                              void* d_out, int out_size) {
    const float* x      = (const float*)d_in[0];
    const float* coords = (const float*)d_in[1];
    const float* Wq     = (const float*)d_in[2];
    const float* Wk     = (const float*)d_in[3];
    const float* Wv     = (const float*)d_in[4];
    const float* ebw1   = (const float*)d_in[5];
    const float* ebb1   = (const float*)d_in[6];
    const float* ebw2   = (const float*)d_in[7];
    const float* ebb2   = (const float*)d_in[8];
    const float* evw1   = (const float*)d_in[9];
    const float* evb1   = (const float*)d_in[10];
    const float* evw2   = (const float*)d_in[11];
    const float* evb2   = (const float*)d_in[12];
    const float* Wo     = (const float*)d_in[13];
    const float* bo     = (const float*)d_in[14];
    const float* ln1w   = (const float*)d_in[15];
    const float* ln1b   = (const float*)d_in[16];
    const float* ln2w   = (const float*)d_in[17];
    const float* ln2b   = (const float*)d_in[18];
    const float* ffw1   = (const float*)d_in[19];
    const float* ffb1   = (const float*)d_in[20];
    const float* ffw2   = (const float*)d_in[21];
    const float* ffb2   = (const float*)d_in[22];

    static float *p_x = nullptr, *p_xn, *p_qkv, *p_wqkv, *p_tmp, *p_hg, *p_Ag;
    if (!p_x) {
        cudaGetSymbolAddress((void**)&p_x,    g_x);
        cudaGetSymbolAddress((void**)&p_xn,   g_xn);
        cudaGetSymbolAddress((void**)&p_qkv,  g_qkv);
        cudaGetSymbolAddress((void**)&p_wqkv, g_wqkv);
        cudaGetSymbolAddress((void**)&p_tmp,  g_tmp);
        cudaGetSymbolAddress((void**)&p_hg,   g_hg);
        cudaGetSymbolAddress((void**)&p_Ag,   g_Ag);
    }

    const int ROWS = BB * NN;   // 1024

    k_loadx<<<ROWS, 256>>>(x);
    k_pack<<<(LL * DD * 768) / 256, 256>>>(Wq, Wk, Wv);
    k_adj_fill<<<ROWS, 64>>>();
    k_knn<<<BB * 32, 64>>>(coords);
    k_elist<<<ROWS, 256>>>();
    k_eb_both<<<296, 256>>>(coords, ebw1, ebb1, ebw2, ebb2);

    for (int l = 0; l < LL; l++) {
        const float* evw1_l = evw1 + (size_t)l * 11 * INNER;
        const float* evb1_l = evb1 + (size_t)l * INNER;
        const float* Wo_l   = Wo   + (size_t)l * INNER * DD;
        const float* bo_l   = bo   + (size_t)l * DD;
        const float* evw2_l = evw2 + (size_t)l * INNER * INNER;
        const float* evb2_l = evb2 + (size_t)l * INNER;
        const float* ffw1_l = ffw1 + (size_t)l * DD * FFH;
        const float* ffb1_l = ffb1 + (size_t)l * FFH;
        const float* ffw2_l = ffw2 + (size_t)l * FFHALF * DD;
        const float* ffb2_l = ffb2 + (size_t)l * DD;

        k_layernorm<<<ROWS, 256>>>(p_x, ln1w + l * DD, ln1b + l * DD, p_xn);
        k_gemm3<false, false, false><<<dim3(768 / 64, ROWS / 32, 1), 64>>>(
            p_xn, p_wqkv + (size_t)l * DD * 768, nullptr, nullptr, p_qkv,
            DD, DD, 768, 768, 0, 0, 0, 0);
        k_attn<<<BB * HH * NN, 256>>>(l);
        k_Ag<<<BB * NN, 256>>>(coords, evw1_l, evb1_l);
        k_gemm3<false, true, true><<<dim3(1, ROWS / 32, HH), 64>>>(
            p_Ag, evw2_l, evb2_l, p_tmp, p_tmp,
            INNER, INNER, INNER, INNER,
            (long)BB * NN * INNER, 64, 64, 64);
        k_gemm3<false, true, true><<<dim3(DD / 64, ROWS / 32, 1), 64>>>(
            p_tmp, Wo_l, bo_l, p_x, p_x,
            INNER, INNER, DD, DD, 0, 0, 0, 0);
        k_layernorm<<<ROWS, 256>>>(p_x, ln2w + l * DD, ln2b + l * DD, p_xn);
        k_gemm3<false, true, false><<<dim3(FFH / 64, ROWS / 32, 1), 64>>>(
            p_xn, ffw1_l, ffb1_l, nullptr, p_hg,
            DD, DD, FFH, FFH, 0, 0, 0, 0);
        float* outC = (l == LL - 1) ? (float*)d_out : p_x;
        k_gemm3<true, true, true><<<dim3(DD / 64, ROWS / 32, 1), 64>>>(
            p_hg, ffw2_l, ffb2_l, p_x, outC,
            FFHALF, FFH, DD, DD, 0, 0, 0, 0);
    }
}